// round 11
// baseline (speedup 1.0000x reference)
#include <cuda_runtime.h>
#include <cuda_fp16.h>
#include <cstdint>

#define NNODES 40000
#define NEDGES_MAX 640000
#define NGRAPHS 128
#define DD 128

// ---------------- scratch (no allocations allowed) ----------------
__device__ __half g_t[(size_t)NNODES * DD];   // GEMM output (fp16 gather payload)
__device__ int    g_deg[NNODES];
__device__ int    g_rowptr[NNODES + 1];
__device__ int    g_cursor[NNODES];
__device__ int    g_partials[256];
__device__ int    g_esrc[NEDGES_MAX];
__device__ float  g_ewr[NEDGES_MAX];
// A fragments (bf16x2 packed, hi/lo) for next-layer GEMM input, fragment order:
// off(row,colpair) = ((mblk*8+ks)*32 + gid*4+tf)*4 + ii    (2500 mblks)
__device__ uint32_t g_ahi[(size_t)(NNODES / 16) * 8 * 32 * 4];
__device__ uint32_t g_alo[(size_t)(NNODES / 16) * 8 * 32 * 4];
// W fragments (bf16x2 packed), hi/lo, fragment-ordered: [layer][hi/lo][8192]
__device__ uint32_t g_wfrag[3][2][8192];

// ======================= bf16-split helpers =======================
__device__ __forceinline__ uint32_t bf16x2_pack(float odd, float even) {
    uint32_t r;   // r[31:16] = bf16(odd), r[15:0] = bf16(even)
    asm("cvt.rn.bf16x2.f32 %0, %1, %2;" : "=r"(r) : "f"(odd), "f"(even));
    return r;
}

__device__ __forceinline__ void split_pair(float xe, float xo,
                                           uint32_t& hi, uint32_t& lo) {
    hi = bf16x2_pack(xo, xe);
    float hef = __uint_as_float(hi << 16);
    float hof = __uint_as_float(hi & 0xffff0000u);
    lo = bf16x2_pack(xo - hof, xe - hef);
}

// A-fragment offset for node row, even col c (pair c, c+1)
__device__ __forceinline__ int afrag_off(int row, int c) {
    int mblk = row >> 4, r = row & 15;
    int gid = r & 7, rb = r >> 3;
    int ks = c >> 4, c16 = c & 15;
    int tf = (c16 & 7) >> 1;
    int ii = ((c16 >> 3) << 1) | rb;
    return ((mblk * 8 + ks) * 32 + (gid * 4 + tf)) * 4 + ii;
}

__device__ __forceinline__ void mma_bf16(float* c, const uint32_t* a, const uint32_t* b) {
    asm volatile(
        "mma.sync.aligned.m16n8k16.row.col.f32.bf16.bf16.f32 "
        "{%0,%1,%2,%3}, {%4,%5,%6,%7}, {%8,%9}, {%0,%1,%2,%3};"
        : "+f"(c[0]), "+f"(c[1]), "+f"(c[2]), "+f"(c[3])
        : "r"(a[0]), "r"(a[1]), "r"(a[2]), "r"(a[3]), "r"(b[0]), "r"(b[1]));
}

// ======================= fragment-direct GEMM =======================
// t[M,128] = A[M,128] @ W[128,128]^T; A already split/fragment-ordered in
// global (g_ahi/g_alo), W fragments in g_wfrag. No smem, no barrier.
// BM=64 (625 CTAs), 8 warps, warp tile 32x32.
__global__ __launch_bounds__(256, 3) void gemm_mma_kernel(
    const uint32_t* __restrict__ ah, const uint32_t* __restrict__ al,
    const uint32_t* __restrict__ wf,
    __half* __restrict__ out, int M)
{
    const int tid  = threadIdx.x;
    const int wid  = tid >> 5;
    const int lane = tid & 31;
    const int wm   = wid >> 2;          // 0..1  (32-row group)
    const int wn   = wid & 3;           // 0..3  (32-col group)
    const int rbase = blockIdx.x * 64;
    const uint32_t* __restrict__ wf_hi = wf;
    const uint32_t* __restrict__ wf_lo = wf + 8192;

    float C[2][4][4];
    #pragma unroll
    for (int i = 0; i < 2; i++)
        #pragma unroll
        for (int j = 0; j < 4; j++)
            #pragma unroll
            for (int q = 0; q < 4; q++) C[i][j][q] = 0.f;

    #pragma unroll
    for (int ks = 0; ks < 8; ks++) {
        uint32_t Ahi[2][4], Alo[2][4], Bhi[4][2], Blo[4][2];
        #pragma unroll
        for (int fm = 0; fm < 2; fm++) {
            int mblkg = (rbase >> 4) + wm * 2 + fm;
            int base = ((mblkg * 8 + ks) * 32 + lane) * 4;
            uint4 h = __ldg((const uint4*)(ah + base));
            uint4 l = __ldg((const uint4*)(al + base));
            Ahi[fm][0] = h.x; Ahi[fm][1] = h.y; Ahi[fm][2] = h.z; Ahi[fm][3] = h.w;
            Alo[fm][0] = l.x; Alo[fm][1] = l.y; Alo[fm][2] = l.z; Alo[fm][3] = l.w;
        }
        #pragma unroll
        for (int fn = 0; fn < 4; fn++) {
            int nblk = wn * 4 + fn;
            int boff = ((nblk * 8 + ks) * 32 + lane) * 2;
            uint2 h = __ldg((const uint2*)(wf_hi + boff));
            uint2 l = __ldg((const uint2*)(wf_lo + boff));
            Bhi[fn][0] = h.x; Bhi[fn][1] = h.y;
            Blo[fn][0] = l.x; Blo[fn][1] = l.y;
        }
        #pragma unroll
        for (int fm = 0; fm < 2; fm++)
            #pragma unroll
            for (int fn = 0; fn < 4; fn++) {
                mma_bf16(C[fm][fn], Ahi[fm], Bhi[fn]);
                mma_bf16(C[fm][fn], Ahi[fm], Blo[fn]);
                mma_bf16(C[fm][fn], Alo[fm], Bhi[fn]);
            }
    }

    // ---- epilogue: write C frags as fp16 ----
    #pragma unroll
    for (int fm = 0; fm < 2; fm++) {
        int row0 = rbase + wm * 32 + fm * 16 + (lane >> 2);
        #pragma unroll
        for (int fn = 0; fn < 4; fn++) {
            int col = wn * 32 + fn * 8 + (lane & 3) * 2;
            if (row0 < M)
                *(__half2*)(out + (size_t)row0 * DD + col) =
                    __float22half2_rn(make_float2(C[fm][fn][0], C[fm][fn][1]));
            if (row0 + 8 < M)
                *(__half2*)(out + (size_t)(row0 + 8) * DD + col) =
                    __float22half2_rn(make_float2(C[fm][fn][2], C[fm][fn][3]));
        }
    }
}

// ---------------- feat -> A-fragment conversion (layer 0, once) ----------------
__global__ void aconv_kernel(const float* __restrict__ A,
                             uint32_t* __restrict__ ah, uint32_t* __restrict__ al,
                             int M)
{
    int idx = blockIdx.x * blockDim.x + threadIdx.x;   // 0..M*32-1
    if (idx >= M * 32) return;
    int row = idx >> 5;
    int q   = idx & 31;
    float4 v = __ldg((const float4*)(A + (size_t)row * DD + q * 4));
    #pragma unroll
    for (int p = 0; p < 2; p++) {
        int c = q * 4 + 2 * p;
        uint32_t hi, lo;
        split_pair(p ? v.z : v.x, p ? v.w : v.y, hi, lo);
        int off = afrag_off(row, c);
        ah[off] = hi;
        al[off] = lo;
    }
}

// ---------------- W fragment precompute (once per call) ----------------
__global__ void wconv_kernel(const float* __restrict__ W0,
                             const float* __restrict__ W1,
                             const float* __restrict__ W2,
                             uint32_t* __restrict__ wf)   // [3][2][8192]
{
    int idx = blockIdx.x * blockDim.x + threadIdx.x;      // 0..24575
    if (idx >= 3 * 8192) return;
    int l   = idx >> 13;
    int rem = idx & 8191;
    int n   = rem >> 6;          // 0..127 (out feature)
    int t   = rem & 63;          // k-pair index, k = 2t
    const float* W = (l == 0) ? W0 : (l == 1) ? W1 : W2;
    float x0 = __ldg(W + (size_t)n * DD + 2 * t);
    float x1 = __ldg(W + (size_t)n * DD + 2 * t + 1);
    uint32_t hi, lo;
    split_pair(x0, x1, hi, lo);
    int ks  = t >> 3;
    int tf  = t & 3;
    int ii  = (t >> 2) & 1;
    int nblk = n >> 3, gid = n & 7;
    int lane = gid * 4 + tf;
    int off = ((nblk * 8 + ks) * 32 + lane) * 2 + ii;
    wf[l * 16384 + off]        = hi;
    wf[l * 16384 + 8192 + off] = lo;
}

// ---------------- CSR build: histogram + 2-level scan + reorder ----------------
__global__ void hist_kernel(const int* __restrict__ col, int* __restrict__ deg, int E)
{
    int e = blockIdx.x * blockDim.x + threadIdx.x;
    if (e < E) atomicAdd(&deg[col[e]], 1);
}

__global__ void block_sum_kernel(const int* __restrict__ deg, int* __restrict__ partials, int N)
{
    __shared__ int s[256];
    int i = blockIdx.x * 256 + threadIdx.x;
    s[threadIdx.x] = (i < N) ? deg[i] : 0;
    __syncthreads();
    for (int off = 128; off > 0; off >>= 1) {
        if (threadIdx.x < off) s[threadIdx.x] += s[threadIdx.x + off];
        __syncthreads();
    }
    if (threadIdx.x == 0) partials[blockIdx.x] = s[0];
}

__global__ void scan_partials_kernel(int* __restrict__ partials, int nb,
                                     int* __restrict__ rowptr, int N)
{
    __shared__ int s[256];
    int t = threadIdx.x;
    int d = (t < nb) ? partials[t] : 0;
    s[t] = d;
    __syncthreads();
    #pragma unroll
    for (int off = 1; off < 256; off <<= 1) {
        int v = (t >= off) ? s[t - off] : 0;
        __syncthreads();
        s[t] += v;
        __syncthreads();
    }
    if (t < nb) partials[t] = s[t] - d;     // exclusive
    if (t == 255) rowptr[N] = s[255];       // grand total = E
}

__global__ void chunk_scan_kernel(const int* __restrict__ deg,
                                  const int* __restrict__ partials,
                                  int* __restrict__ rowptr, int* __restrict__ cursor, int N)
{
    __shared__ int s[256];
    int t = threadIdx.x;
    int i = blockIdx.x * 256 + t;
    int d = (i < N) ? deg[i] : 0;
    s[t] = d;
    __syncthreads();
    #pragma unroll
    for (int off = 1; off < 256; off <<= 1) {
        int v = (t >= off) ? s[t - off] : 0;
        __syncthreads();
        s[t] += v;
        __syncthreads();
    }
    if (i < N) {
        int val = partials[blockIdx.x] + s[t] - d;   // exclusive global prefix
        rowptr[i] = val;
        cursor[i] = val;
    }
}

__global__ void fill_kernel(const int* __restrict__ row, const int* __restrict__ col,
                            const float* __restrict__ ew,
                            int* __restrict__ cursor,
                            int* __restrict__ esrc, float* __restrict__ ewr, int E)
{
    int e = blockIdx.x * blockDim.x + threadIdx.x;
    if (e >= E) return;
    int c = col[e];
    int p = atomicAdd(&cursor[c], 1);
    esrc[p] = row[e];
    ewr[p]  = ew[e];
}

// ---------------- fused aggregate (CSR fp16 gather) + PReLU + pool ----------------
// Serial edge loop (R8 form). Output: fragment hi/lo (layers 0,1) or fp32 (layer 2).
__device__ __forceinline__ void red_add_v4(float* dst, float4 v) {
    asm volatile("red.global.add.v4.f32 [%0], {%1, %2, %3, %4};"
                 :: "l"(dst), "f"(v.x), "f"(v.y), "f"(v.z), "f"(v.w)
                 : "memory");
}

__global__ __launch_bounds__(256) void aggregate_pool_kernel(
    const __half* __restrict__ t, const int* __restrict__ rowptr,
    const int* __restrict__ esrc, const float* __restrict__ ewr,
    const float* __restrict__ aptr, const int* __restrict__ batch,
    float* __restrict__ hout,                 // fp32 out (layer 2) or null
    uint32_t* __restrict__ fh, uint32_t* __restrict__ fl,  // frag out (layers 0,1)
    float* __restrict__ hg, int N, int loff)
{
    int wid  = (blockIdx.x * blockDim.x + threadIdx.x) >> 5;
    int lane = threadIdx.x & 31;
    int n0 = wid * 4;
    if (n0 >= N) return;
    float alpha = __ldg(aptr);

    float4 run = make_float4(0.f, 0.f, 0.f, 0.f);
    int curg = -1;
    int nend = n0 + 4; if (nend > N) nend = N;

    for (int n = n0; n < nend; n++) {
        int jb = __ldg(rowptr + n);
        int je = __ldg(rowptr + n + 1);
        float4 acc = make_float4(0.f, 0.f, 0.f, 0.f);
        for (int j = jb; j < je; j++) {
            int r   = __ldg(esrc + j);
            float w = __ldg(ewr + j);
            uint2 u = __ldg((const uint2*)(t + (size_t)r * DD) + lane);
            float2 f01 = __half22float2(*reinterpret_cast<__half2*>(&u.x));
            float2 f23 = __half22float2(*reinterpret_cast<__half2*>(&u.y));
            acc.x = fmaf(f01.x, w, acc.x);
            acc.y = fmaf(f01.y, w, acc.y);
            acc.z = fmaf(f23.x, w, acc.z);
            acc.w = fmaf(f23.y, w, acc.w);
        }
        float4 p;
        p.x = acc.x >= 0.f ? acc.x : alpha * acc.x;
        p.y = acc.y >= 0.f ? acc.y : alpha * acc.y;
        p.z = acc.z >= 0.f ? acc.z : alpha * acc.z;
        p.w = acc.w >= 0.f ? acc.w : alpha * acc.w;

        if (fh) {
            #pragma unroll
            for (int pp = 0; pp < 2; pp++) {
                int c = 4 * lane + 2 * pp;
                uint32_t hi, lo;
                split_pair(pp ? p.z : p.x, pp ? p.w : p.y, hi, lo);
                int off = afrag_off(n, c);
                fh[off] = hi;
                fl[off] = lo;
            }
        } else {
            *(float4*)(hout + (size_t)n * DD + lane * 4) = p;
        }

        int g = __ldg(batch + n);
        if (g != curg) {
            if (curg >= 0)
                red_add_v4(hg + (size_t)curg * (3 * DD) + loff + lane * 4, run);
            curg = g;
            run = p;
        } else {
            run.x += p.x; run.y += p.y; run.z += p.z; run.w += p.w;
        }
    }
    if (curg >= 0)
        red_add_v4(hg + (size_t)curg * (3 * DD) + loff + lane * 4, run);
}

// ---------------- launch ----------------
extern "C" void kernel_launch(void* const* d_in, const int* in_sizes, int n_in,
                              void* d_out, int out_size)
{
    const float* feat  = (const float*)d_in[0];
    const float* ew    = (const float*)d_in[1];
    const float* W[3]  = {(const float*)d_in[2], (const float*)d_in[3], (const float*)d_in[4]};
    const float* a[3]  = {(const float*)d_in[5], (const float*)d_in[6], (const float*)d_in[7]};
    const int*   eidx  = (const int*)d_in[8];
    const int*   batch = (const int*)d_in[9];

    const int N = in_sizes[0] / DD;      // 40000
    const int E = in_sizes[1];           // 640000
    const int* rowp = eidx;
    const int* colp = eidx + E;

    float *ewr_ptr;
    __half* t_ptr;
    int *deg_ptr, *rowptr_ptr, *cursor_ptr, *partials_ptr, *esrc_ptr;
    uint32_t *wf_ptr, *ahi_ptr, *alo_ptr;
    cudaGetSymbolAddress((void**)&t_ptr,       g_t);
    cudaGetSymbolAddress((void**)&deg_ptr,     g_deg);
    cudaGetSymbolAddress((void**)&rowptr_ptr,  g_rowptr);
    cudaGetSymbolAddress((void**)&cursor_ptr,  g_cursor);
    cudaGetSymbolAddress((void**)&partials_ptr,g_partials);
    cudaGetSymbolAddress((void**)&esrc_ptr,    g_esrc);
    cudaGetSymbolAddress((void**)&ewr_ptr,     g_ewr);
    cudaGetSymbolAddress((void**)&wf_ptr,      g_wfrag);
    cudaGetSymbolAddress((void**)&ahi_ptr,     g_ahi);
    cudaGetSymbolAddress((void**)&alo_ptr,     g_alo);

    float* h_out = (float*)d_out;                         // (N, 128)
    float* hg    = (float*)d_out + (size_t)N * DD;        // (128, 384)

    cudaStream_t s = 0;
    cudaMemsetAsync(hg, 0, (size_t)NGRAPHS * 3 * DD * sizeof(float), s);   // launch 1
    cudaMemsetAsync(deg_ptr, 0, (size_t)N * sizeof(int), s);               // launch 2

    const int nb = (N + 255) / 256;      // 157 chunks
    const int gemm_blocks = (N + 63) / 64;
    const int agg_warps   = (N + 3) / 4;
    const int agg_blocks  = (agg_warps * 32 + 255) / 256;

    // Ordered so that launch #6 (ncu -s 5 -c 1) is the GEMM.
    wconv_kernel<<<(3 * 8192 + 255) / 256, 256, 0, s>>>(W[0], W[1], W[2], wf_ptr);  // 3
    aconv_kernel<<<(N * 32 + 255) / 256, 256, 0, s>>>(feat, ahi_ptr, alo_ptr, N);   // 4
    hist_kernel<<<(E + 255) / 256, 256, 0, s>>>(colp, deg_ptr, E);                  // 5
    gemm_mma_kernel<<<gemm_blocks, 256, 0, s>>>(ahi_ptr, alo_ptr, wf_ptr, t_ptr, N);// 6 <- profiled
    block_sum_kernel<<<nb, 256, 0, s>>>(deg_ptr, partials_ptr, N);                  // 7
    scan_partials_kernel<<<1, 256, 0, s>>>(partials_ptr, nb, rowptr_ptr, N);        // 8
    chunk_scan_kernel<<<nb, 256, 0, s>>>(deg_ptr, partials_ptr, rowptr_ptr, cursor_ptr, N); // 9
    fill_kernel<<<(E + 255) / 256, 256, 0, s>>>(rowp, colp, ew, cursor_ptr, esrc_ptr, ewr_ptr, E); // 10

    // layer 0: aggregate -> fragment output (input of layer-1 GEMM)
    aggregate_pool_kernel<<<agg_blocks, 256, 0, s>>>(
        t_ptr, rowptr_ptr, esrc_ptr, ewr_ptr, a[0], batch,
        nullptr, ahi_ptr, alo_ptr, hg, N, 0);                                       // 11

    // layer 1
    gemm_mma_kernel<<<gemm_blocks, 256, 0, s>>>(ahi_ptr, alo_ptr, wf_ptr + 16384, t_ptr, N);
    aggregate_pool_kernel<<<agg_blocks, 256, 0, s>>>(
        t_ptr, rowptr_ptr, esrc_ptr, ewr_ptr, a[1], batch,
        nullptr, ahi_ptr, alo_ptr, hg, N, DD);

    // layer 2: aggregate -> fp32 d_out
    gemm_mma_kernel<<<gemm_blocks, 256, 0, s>>>(ahi_ptr, alo_ptr, wf_ptr + 32768, t_ptr, N);
    aggregate_pool_kernel<<<agg_blocks, 256, 0, s>>>(
        t_ptr, rowptr_ptr, esrc_ptr, ewr_ptr, a[2], batch,
        h_out, nullptr, nullptr, hg, N, 2 * DD);
}

// round 12
// speedup vs baseline: 1.0528x; 1.0528x over previous
#include <cuda_runtime.h>
#include <cuda_fp16.h>
#include <cstdint>

#define NNODES 40000
#define NEDGES_MAX 640000
#define NGRAPHS 128
#define DD 128

// ---------------- scratch (no allocations allowed) ----------------
__device__ __half g_t[(size_t)NNODES * DD];   // GEMM output (fp16 gather payload)
__device__ float  g_h[(size_t)NNODES * DD];   // layer output (next-layer input)
__device__ int    g_deg[NNODES];
__device__ int    g_rowptr[NNODES + 1];
__device__ int    g_cursor[NNODES];
__device__ int    g_partials[256];
__device__ int2   g_epack[NEDGES_MAX];        // (src, __float_as_int(weight))
// W fragments (bf16x2 packed), hi/lo, fragment-ordered: [layer][hi/lo][8192]
__device__ uint32_t g_wfrag[3][2][8192];

// ======================= bf16-split tensor GEMM (mma.sync m16n8k16) ============
// t[M,128] = A[M,128] @ W[128,128]^T (fp32 accuracy via hi/lo bf16 split),
// epilogue converts to fp16 (t feeds only the edge-gather aggregate).
// BM=64 (625 CTAs), BN=128, 8 warps, warp tile 32x32, smem-staged A (R10 form).

__device__ __forceinline__ uint32_t bf16x2_pack(float odd, float even) {
    uint32_t r;   // r[31:16] = bf16(odd), r[15:0] = bf16(even)
    asm("cvt.rn.bf16x2.f32 %0, %1, %2;" : "=r"(r) : "f"(odd), "f"(even));
    return r;
}

__device__ __forceinline__ void mma_bf16(float* c, const uint32_t* a, const uint32_t* b) {
    asm volatile(
        "mma.sync.aligned.m16n8k16.row.col.f32.bf16.bf16.f32 "
        "{%0,%1,%2,%3}, {%4,%5,%6,%7}, {%8,%9}, {%0,%1,%2,%3};"
        : "+f"(c[0]), "+f"(c[1]), "+f"(c[2]), "+f"(c[3])
        : "r"(a[0]), "r"(a[1]), "r"(a[2]), "r"(a[3]), "r"(b[0]), "r"(b[1]));
}

// smem uint32 offsets (A tile only: 64 rows x 64 bf16x2, hi + lo = 32 KB)
#define SA_HI 0
#define SA_LO 4096

__global__ __launch_bounds__(256, 3) void gemm_mma_kernel(
    const float* __restrict__ A, const uint32_t* __restrict__ wf,
    __half* __restrict__ out, int M)
{
    __shared__ uint32_t smem[8192];
    const int tid  = threadIdx.x;
    const int wid  = tid >> 5;
    const int lane = tid & 31;
    const int wm   = wid >> 2;          // 0..1  (32-row group)
    const int wn   = wid & 3;           // 0..3  (32-col group)
    const int rbase = blockIdx.x * 64;
    const uint32_t* __restrict__ wf_hi = wf;
    const uint32_t* __restrict__ wf_lo = wf + 8192;

    float C[2][4][4];
    #pragma unroll
    for (int i = 0; i < 2; i++)
        #pragma unroll
        for (int j = 0; j < 4; j++)
            #pragma unroll
            for (int q = 0; q < 4; q++) C[i][j][q] = 0.f;

    // ---- convert A (64x128) into fragment-ordered bf16x2 SMEM hi/lo ----
    #pragma unroll
    for (int rep = 0; rep < 8; rep++) {
        int idx = rep * 256 + tid;          // 0..2047
        int row = idx >> 5;                 // 0..63
        int q   = idx & 31;                 // float4 index in row
        int gr  = rbase + row;
        float4 v = (gr < M)
            ? __ldg((const float4*)(A + (size_t)gr * DD + q * 4))
            : make_float4(0.f, 0.f, 0.f, 0.f);
        int mblk = row >> 4, r = row & 15;
        int gid = r & 7, rb = r >> 3;
        int ks  = q >> 2;                   // k16 step
        int c15 = (q & 3) * 4;              // col within 16-block (0,4,8,12)
        float e[4] = {v.x, v.y, v.z, v.w};
        #pragma unroll
        for (int p = 0; p < 2; p++) {
            int c = c15 + 2 * p;
            int tf = (c & 7) >> 1;
            int ii = ((c >> 3) << 1) | rb;
            float xe = e[2 * p], xo = e[2 * p + 1];
            uint32_t hi = bf16x2_pack(xo, xe);
            float hef = __uint_as_float(hi << 16);
            float hof = __uint_as_float(hi & 0xffff0000u);
            uint32_t lo = bf16x2_pack(xo - hof, xe - hef);
            int slot = ((gid << 2) | tf) ^ ks;      // lane swizzle vs ks
            int off = ((mblk * 8 + ks) * 32 + slot) * 4 + ii;
            smem[SA_HI + off] = hi;
            smem[SA_LO + off] = lo;
        }
    }
    __syncthreads();

    // ---- 8 k16-steps of m16n8k16, 3 split terms each ----
    #pragma unroll
    for (int ks = 0; ks < 8; ks++) {
        uint32_t Ahi[2][4], Alo[2][4], Bhi[4][2], Blo[4][2];
        #pragma unroll
        for (int fm = 0; fm < 2; fm++) {
            int mblk = wm * 2 + fm;
            int base = ((mblk * 8 + ks) * 32 + (lane ^ ks)) * 4;
            uint4 h = *(const uint4*)(smem + SA_HI + base);
            uint4 l = *(const uint4*)(smem + SA_LO + base);
            Ahi[fm][0] = h.x; Ahi[fm][1] = h.y; Ahi[fm][2] = h.z; Ahi[fm][3] = h.w;
            Alo[fm][0] = l.x; Alo[fm][1] = l.y; Alo[fm][2] = l.z; Alo[fm][3] = l.w;
        }
        #pragma unroll
        for (int fn = 0; fn < 4; fn++) {
            int nblk = wn * 4 + fn;
            int boff = ((nblk * 8 + ks) * 32 + lane) * 2;
            uint2 h = __ldg((const uint2*)(wf_hi + boff));
            uint2 l = __ldg((const uint2*)(wf_lo + boff));
            Bhi[fn][0] = h.x; Bhi[fn][1] = h.y;
            Blo[fn][0] = l.x; Blo[fn][1] = l.y;
        }
        #pragma unroll
        for (int fm = 0; fm < 2; fm++)
            #pragma unroll
            for (int fn = 0; fn < 4; fn++) {
                mma_bf16(C[fm][fn], Ahi[fm], Bhi[fn]);
                mma_bf16(C[fm][fn], Ahi[fm], Blo[fn]);
                mma_bf16(C[fm][fn], Alo[fm], Bhi[fn]);
            }
    }

    // ---- epilogue: write C frags as fp16 ----
    #pragma unroll
    for (int fm = 0; fm < 2; fm++) {
        int row0 = rbase + wm * 32 + fm * 16 + (lane >> 2);
        #pragma unroll
        for (int fn = 0; fn < 4; fn++) {
            int col = wn * 32 + fn * 8 + (lane & 3) * 2;
            if (row0 < M)
                *(__half2*)(out + (size_t)row0 * DD + col) =
                    __float22half2_rn(make_float2(C[fm][fn][0], C[fm][fn][1]));
            if (row0 + 8 < M)
                *(__half2*)(out + (size_t)(row0 + 8) * DD + col) =
                    __float22half2_rn(make_float2(C[fm][fn][2], C[fm][fn][3]));
        }
    }
}

// ---------------- W fragment precompute (once per call) ----------------
__global__ void wconv_kernel(const float* __restrict__ W0,
                             const float* __restrict__ W1,
                             const float* __restrict__ W2,
                             uint32_t* __restrict__ wf)   // [3][2][8192]
{
    int idx = blockIdx.x * blockDim.x + threadIdx.x;      // 0..24575
    if (idx >= 3 * 8192) return;
    int l   = idx >> 13;
    int rem = idx & 8191;
    int n   = rem >> 6;          // 0..127 (out feature)
    int t   = rem & 63;          // k-pair index, k = 2t
    const float* W = (l == 0) ? W0 : (l == 1) ? W1 : W2;
    float x0 = __ldg(W + (size_t)n * DD + 2 * t);
    float x1 = __ldg(W + (size_t)n * DD + 2 * t + 1);
    uint32_t hi = bf16x2_pack(x1, x0);
    float h0 = __uint_as_float(hi << 16);
    float h1 = __uint_as_float(hi & 0xffff0000u);
    uint32_t lo = bf16x2_pack(x1 - h1, x0 - h0);
    int ks  = t >> 3;
    int tf  = t & 3;
    int ii  = (t >> 2) & 1;
    int nblk = n >> 3, gid = n & 7;
    int lane = gid * 4 + tf;
    int off = ((nblk * 8 + ks) * 32 + lane) * 2 + ii;
    wf[l * 16384 + off]        = hi;
    wf[l * 16384 + 8192 + off] = lo;
}

// ---------------- CSR build: histogram + 2-level scan + reorder ----------------
__global__ void hist_kernel(const int* __restrict__ col, int* __restrict__ deg, int E)
{
    int e = blockIdx.x * blockDim.x + threadIdx.x;
    if (e < E) atomicAdd(&deg[col[e]], 1);
}

__global__ void block_sum_kernel(const int* __restrict__ deg, int* __restrict__ partials, int N)
{
    __shared__ int s[256];
    int i = blockIdx.x * 256 + threadIdx.x;
    s[threadIdx.x] = (i < N) ? deg[i] : 0;
    __syncthreads();
    for (int off = 128; off > 0; off >>= 1) {
        if (threadIdx.x < off) s[threadIdx.x] += s[threadIdx.x + off];
        __syncthreads();
    }
    if (threadIdx.x == 0) partials[blockIdx.x] = s[0];
}

__global__ void scan_partials_kernel(int* __restrict__ partials, int nb,
                                     int* __restrict__ rowptr, int N)
{
    __shared__ int s[256];
    int t = threadIdx.x;
    int d = (t < nb) ? partials[t] : 0;
    s[t] = d;
    __syncthreads();
    #pragma unroll
    for (int off = 1; off < 256; off <<= 1) {
        int v = (t >= off) ? s[t - off] : 0;
        __syncthreads();
        s[t] += v;
        __syncthreads();
    }
    if (t < nb) partials[t] = s[t] - d;     // exclusive
    if (t == 255) rowptr[N] = s[255];       // grand total = E
}

__global__ void chunk_scan_kernel(const int* __restrict__ deg,
                                  const int* __restrict__ partials,
                                  int* __restrict__ rowptr, int* __restrict__ cursor, int N)
{
    __shared__ int s[256];
    int t = threadIdx.x;
    int i = blockIdx.x * 256 + t;
    int d = (i < N) ? deg[i] : 0;
    s[t] = d;
    __syncthreads();
    #pragma unroll
    for (int off = 1; off < 256; off <<= 1) {
        int v = (t >= off) ? s[t - off] : 0;
        __syncthreads();
        s[t] += v;
        __syncthreads();
    }
    if (i < N) {
        int val = partials[blockIdx.x] + s[t] - d;   // exclusive global prefix
        rowptr[i] = val;
        cursor[i] = val;
    }
}

__global__ void fill_kernel(const int* __restrict__ row, const int* __restrict__ col,
                            const float* __restrict__ ew,
                            int* __restrict__ cursor,
                            int2* __restrict__ epack, int E)
{
    int e = blockIdx.x * blockDim.x + threadIdx.x;
    if (e >= E) return;
    int c = col[e];
    int p = atomicAdd(&cursor[c], 1);
    epack[p] = make_int2(row[e], __float_as_int(ew[e]));
}

// ---------------- fused aggregate (CSR fp16 gather) + PReLU + pool ----------------
// Serial edge loop (R8 form — no manual unroll), packed (src,w) edge stream,
// 2 nodes per warp for more independent chains.
__device__ __forceinline__ void red_add_v4(float* dst, float4 v) {
    asm volatile("red.global.add.v4.f32 [%0], {%1, %2, %3, %4};"
                 :: "l"(dst), "f"(v.x), "f"(v.y), "f"(v.z), "f"(v.w)
                 : "memory");
}

__global__ __launch_bounds__(256) void aggregate_pool_kernel(
    const __half* __restrict__ t, const int* __restrict__ rowptr,
    const int2* __restrict__ epack,
    const float* __restrict__ aptr, const int* __restrict__ batch,
    float* __restrict__ hout, float* __restrict__ hg, int N, int loff)
{
    int wid  = (blockIdx.x * blockDim.x + threadIdx.x) >> 5;
    int lane = threadIdx.x & 31;
    int n0 = wid * 2;
    if (n0 >= N) return;
    float alpha = __ldg(aptr);

    float4 run = make_float4(0.f, 0.f, 0.f, 0.f);
    int curg = -1;
    int nend = n0 + 2; if (nend > N) nend = N;

    for (int n = n0; n < nend; n++) {
        int jb = __ldg(rowptr + n);
        int je = __ldg(rowptr + n + 1);
        float4 acc = make_float4(0.f, 0.f, 0.f, 0.f);
        for (int j = jb; j < je; j++) {
            int2 e = __ldg(epack + j);
            float w = __int_as_float(e.y);
            uint2 u = __ldg((const uint2*)(t + (size_t)e.x * DD) + lane);
            float2 f01 = __half22float2(*reinterpret_cast<__half2*>(&u.x));
            float2 f23 = __half22float2(*reinterpret_cast<__half2*>(&u.y));
            acc.x = fmaf(f01.x, w, acc.x);
            acc.y = fmaf(f01.y, w, acc.y);
            acc.z = fmaf(f23.x, w, acc.z);
            acc.w = fmaf(f23.y, w, acc.w);
        }
        float4 p;
        p.x = acc.x >= 0.f ? acc.x : alpha * acc.x;
        p.y = acc.y >= 0.f ? acc.y : alpha * acc.y;
        p.z = acc.z >= 0.f ? acc.z : alpha * acc.z;
        p.w = acc.w >= 0.f ? acc.w : alpha * acc.w;
        *(float4*)(hout + (size_t)n * DD + lane * 4) = p;

        int g = __ldg(batch + n);
        if (g != curg) {
            if (curg >= 0)
                red_add_v4(hg + (size_t)curg * (3 * DD) + loff + lane * 4, run);
            curg = g;
            run = p;
        } else {
            run.x += p.x; run.y += p.y; run.z += p.z; run.w += p.w;
        }
    }
    if (curg >= 0)
        red_add_v4(hg + (size_t)curg * (3 * DD) + loff + lane * 4, run);
}

// ---------------- launch ----------------
extern "C" void kernel_launch(void* const* d_in, const int* in_sizes, int n_in,
                              void* d_out, int out_size)
{
    const float* feat  = (const float*)d_in[0];
    const float* ew    = (const float*)d_in[1];
    const float* W[3]  = {(const float*)d_in[2], (const float*)d_in[3], (const float*)d_in[4]};
    const float* a[3]  = {(const float*)d_in[5], (const float*)d_in[6], (const float*)d_in[7]};
    const int*   eidx  = (const int*)d_in[8];
    const int*   batch = (const int*)d_in[9];

    const int N = in_sizes[0] / DD;      // 40000
    const int E = in_sizes[1];           // 640000
    const int* rowp = eidx;
    const int* colp = eidx + E;

    float *h_ptr;
    __half* t_ptr;
    int *deg_ptr, *rowptr_ptr, *cursor_ptr, *partials_ptr;
    int2* epack_ptr;
    uint32_t* wf_ptr;
    cudaGetSymbolAddress((void**)&t_ptr,       g_t);
    cudaGetSymbolAddress((void**)&h_ptr,       g_h);
    cudaGetSymbolAddress((void**)&deg_ptr,     g_deg);
    cudaGetSymbolAddress((void**)&rowptr_ptr,  g_rowptr);
    cudaGetSymbolAddress((void**)&cursor_ptr,  g_cursor);
    cudaGetSymbolAddress((void**)&partials_ptr,g_partials);
    cudaGetSymbolAddress((void**)&epack_ptr,   g_epack);
    cudaGetSymbolAddress((void**)&wf_ptr,      g_wfrag);

    float* h_out = (float*)d_out;                         // (N, 128)
    float* hg    = (float*)d_out + (size_t)N * DD;        // (128, 384)

    cudaStream_t s = 0;
    cudaMemsetAsync(hg, 0, (size_t)NGRAPHS * 3 * DD * sizeof(float), s);   // launch 1
    cudaMemsetAsync(deg_ptr, 0, (size_t)N * sizeof(int), s);               // launch 2

    const int nb = (N + 255) / 256;      // 157 chunks
    const int gemm_blocks = (N + 63) / 64;
    const int agg_warps   = (N + 1) / 2;
    const int agg_blocks  = (agg_warps * 32 + 255) / 256;

    // Ordered so that launch #6 (ncu -s 5 -c 1) is the GEMM.
    wconv_kernel<<<(3 * 8192 + 255) / 256, 256, 0, s>>>(W[0], W[1], W[2], wf_ptr);  // 3
    hist_kernel<<<(E + 255) / 256, 256, 0, s>>>(colp, deg_ptr, E);                  // 4
    block_sum_kernel<<<nb, 256, 0, s>>>(deg_ptr, partials_ptr, N);                  // 5
    gemm_mma_kernel<<<gemm_blocks, 256, 0, s>>>(feat, wf_ptr, t_ptr, N);            // 6 <- profiled
    scan_partials_kernel<<<1, 256, 0, s>>>(partials_ptr, nb, rowptr_ptr, N);        // 7
    chunk_scan_kernel<<<nb, 256, 0, s>>>(deg_ptr, partials_ptr, rowptr_ptr, cursor_ptr, N); // 8
    fill_kernel<<<(E + 255) / 256, 256, 0, s>>>(rowp, colp, ew, cursor_ptr, epack_ptr, E);  // 9

    aggregate_pool_kernel<<<agg_blocks, 256, 0, s>>>(
        t_ptr, rowptr_ptr, epack_ptr, a[0], batch, h_ptr, hg, N, 0);                // 10

    for (int l = 1; l < 3; l++) {
        gemm_mma_kernel<<<gemm_blocks, 256, 0, s>>>(h_ptr, wf_ptr + (size_t)l * 16384, t_ptr, N);
        float* ho = (l == 2) ? h_out : h_ptr;
        aggregate_pool_kernel<<<agg_blocks, 256, 0, s>>>(
            t_ptr, rowptr_ptr, epack_ptr, a[l], batch, ho, hg, N, l * DD);
    }
}

// round 13
// speedup vs baseline: 1.2340x; 1.1721x over previous
#include <cuda_runtime.h>
#include <cuda_fp16.h>
#include <cstdint>

#define NNODES 40000
#define NEDGES_MAX 640000
#define NGRAPHS 128
#define DD 128

// ---------------- scratch (no allocations allowed) ----------------
__device__ __half g_t[(size_t)NNODES * DD];   // GEMM output (fp16 gather payload)
__device__ float  g_h[(size_t)NNODES * DD];   // layer output (next-layer input)
__device__ int    g_deg[NNODES];
__device__ int    g_rowptr[NNODES + 1];
__device__ int    g_cursor[NNODES];
__device__ int    g_partials[256];
__device__ int    g_esrc[NEDGES_MAX];
__device__ float  g_ewr[NEDGES_MAX];
// W fragments (fp16x2 packed, hi only — W quantized to fp16), fragment-ordered
__device__ uint32_t g_wfrag[3][8192];

// ======================= fp16 2-term tensor GEMM (mma.sync m16n8k16) ============
// t[M,128] = A[M,128] @ fp16(W)[128,128]^T with A split exactly into fp16 hi+lo:
//   A*W ~= Ahi*Whi + Alo*Whi   (fp32 accumulate; == exact-A x fp16-quantized-W)
// BM=64 (625 CTAs), BN=128, 8 warps, warp tile 32x32, smem-staged A.

__device__ __forceinline__ uint32_t f16x2_pack(float even, float odd) {
    __half2 h = __float22half2_rn(make_float2(even, odd));  // .x = even (low half)
    return *reinterpret_cast<uint32_t*>(&h);
}

__device__ __forceinline__ void mma_f16(float* c, const uint32_t* a, const uint32_t* b) {
    asm volatile(
        "mma.sync.aligned.m16n8k16.row.col.f32.f16.f16.f32 "
        "{%0,%1,%2,%3}, {%4,%5,%6,%7}, {%8,%9}, {%0,%1,%2,%3};"
        : "+f"(c[0]), "+f"(c[1]), "+f"(c[2]), "+f"(c[3])
        : "r"(a[0]), "r"(a[1]), "r"(a[2]), "r"(a[3]), "r"(b[0]), "r"(b[1]));
}

// smem uint32 offsets (A tile: 64 rows x 64 f16x2, hi + lo = 32 KB)
#define SA_HI 0
#define SA_LO 4096

__global__ __launch_bounds__(256, 3) void gemm_mma_kernel(
    const float* __restrict__ A, const uint32_t* __restrict__ wf,
    __half* __restrict__ out, int M)
{
    __shared__ uint32_t smem[8192];
    const int tid  = threadIdx.x;
    const int wid  = tid >> 5;
    const int lane = tid & 31;
    const int wm   = wid >> 2;          // 0..1  (32-row group)
    const int wn   = wid & 3;           // 0..3  (32-col group)
    const int rbase = blockIdx.x * 64;

    float C[2][4][4];
    #pragma unroll
    for (int i = 0; i < 2; i++)
        #pragma unroll
        for (int j = 0; j < 4; j++)
            #pragma unroll
            for (int q = 0; q < 4; q++) C[i][j][q] = 0.f;

    // ---- convert A (64x128) into fragment-ordered fp16x2 SMEM hi/lo ----
    #pragma unroll
    for (int rep = 0; rep < 8; rep++) {
        int idx = rep * 256 + tid;          // 0..2047
        int row = idx >> 5;                 // 0..63
        int q   = idx & 31;                 // float4 index in row
        int gr  = rbase + row;
        float4 v = (gr < M)
            ? __ldg((const float4*)(A + (size_t)gr * DD + q * 4))
            : make_float4(0.f, 0.f, 0.f, 0.f);
        int mblk = row >> 4, r = row & 15;
        int gid = r & 7, rb = r >> 3;
        int ks  = q >> 2;                   // k16 step
        int c15 = (q & 3) * 4;              // col within 16-block (0,4,8,12)
        float e[4] = {v.x, v.y, v.z, v.w};
        #pragma unroll
        for (int p = 0; p < 2; p++) {
            int c = c15 + 2 * p;
            int tf = (c & 7) >> 1;
            int ii = ((c >> 3) << 1) | rb;
            float xe = e[2 * p], xo = e[2 * p + 1];
            uint32_t hi = f16x2_pack(xe, xo);
            __half2 hh = *reinterpret_cast<__half2*>(&hi);
            float2 hf = __half22float2(hh);
            uint32_t lo = f16x2_pack(xe - hf.x, xo - hf.y);
            int slot = ((gid << 2) | tf) ^ ks;      // lane swizzle vs ks
            int off = ((mblk * 8 + ks) * 32 + slot) * 4 + ii;
            smem[SA_HI + off] = hi;
            smem[SA_LO + off] = lo;
        }
    }
    __syncthreads();

    // ---- 8 k16-steps of m16n8k16, 2 split terms each ----
    #pragma unroll
    for (int ks = 0; ks < 8; ks++) {
        uint32_t Ahi[2][4], Alo[2][4], Bhi[4][2];
        #pragma unroll
        for (int fm = 0; fm < 2; fm++) {
            int mblk = wm * 2 + fm;
            int base = ((mblk * 8 + ks) * 32 + (lane ^ ks)) * 4;
            uint4 h = *(const uint4*)(smem + SA_HI + base);
            uint4 l = *(const uint4*)(smem + SA_LO + base);
            Ahi[fm][0] = h.x; Ahi[fm][1] = h.y; Ahi[fm][2] = h.z; Ahi[fm][3] = h.w;
            Alo[fm][0] = l.x; Alo[fm][1] = l.y; Alo[fm][2] = l.z; Alo[fm][3] = l.w;
        }
        #pragma unroll
        for (int fn = 0; fn < 4; fn++) {
            int nblk = wn * 4 + fn;
            int boff = ((nblk * 8 + ks) * 32 + lane) * 2;
            uint2 h = __ldg((const uint2*)(wf + boff));
            Bhi[fn][0] = h.x; Bhi[fn][1] = h.y;
        }
        #pragma unroll
        for (int fm = 0; fm < 2; fm++)
            #pragma unroll
            for (int fn = 0; fn < 4; fn++) {
                mma_f16(C[fm][fn], Ahi[fm], Bhi[fn]);
                mma_f16(C[fm][fn], Alo[fm], Bhi[fn]);
            }
    }

    // ---- epilogue: write C frags as fp16 ----
    #pragma unroll
    for (int fm = 0; fm < 2; fm++) {
        int row0 = rbase + wm * 32 + fm * 16 + (lane >> 2);
        #pragma unroll
        for (int fn = 0; fn < 4; fn++) {
            int col = wn * 32 + fn * 8 + (lane & 3) * 2;
            if (row0 < M)
                *(__half2*)(out + (size_t)row0 * DD + col) =
                    __float22half2_rn(make_float2(C[fm][fn][0], C[fm][fn][1]));
            if (row0 + 8 < M)
                *(__half2*)(out + (size_t)(row0 + 8) * DD + col) =
                    __float22half2_rn(make_float2(C[fm][fn][2], C[fm][fn][3]));
        }
    }
}

// ---------------- W fragment precompute (once per call) ----------------
__global__ void wconv_kernel(const float* __restrict__ W0,
                             const float* __restrict__ W1,
                             const float* __restrict__ W2,
                             uint32_t* __restrict__ wf)   // [3][8192]
{
    int idx = blockIdx.x * blockDim.x + threadIdx.x;      // 0..24575
    if (idx >= 3 * 8192) return;
    int l   = idx >> 13;
    int rem = idx & 8191;
    int n   = rem >> 6;          // 0..127 (out feature)
    int t   = rem & 63;          // k-pair index, k = 2t
    const float* W = (l == 0) ? W0 : (l == 1) ? W1 : W2;
    float x0 = __ldg(W + (size_t)n * DD + 2 * t);
    float x1 = __ldg(W + (size_t)n * DD + 2 * t + 1);
    uint32_t hi = f16x2_pack(x0, x1);
    int ks  = t >> 3;
    int tf  = t & 3;
    int ii  = (t >> 2) & 1;
    int nblk = n >> 3, gid = n & 7;
    int lane = gid * 4 + tf;
    int off = ((nblk * 8 + ks) * 32 + lane) * 2 + ii;
    wf[l * 8192 + off] = hi;
}

// ---------------- CSR build: histogram + 2-level scan + reorder ----------------
__global__ void hist_kernel(const int* __restrict__ col, int* __restrict__ deg, int E)
{
    int e = blockIdx.x * blockDim.x + threadIdx.x;
    if (e < E) atomicAdd(&deg[col[e]], 1);
}

__global__ void block_sum_kernel(const int* __restrict__ deg, int* __restrict__ partials, int N)
{
    __shared__ int s[256];
    int i = blockIdx.x * 256 + threadIdx.x;
    s[threadIdx.x] = (i < N) ? deg[i] : 0;
    __syncthreads();
    for (int off = 128; off > 0; off >>= 1) {
        if (threadIdx.x < off) s[threadIdx.x] += s[threadIdx.x + off];
        __syncthreads();
    }
    if (threadIdx.x == 0) partials[blockIdx.x] = s[0];
}

__global__ void scan_partials_kernel(int* __restrict__ partials, int nb,
                                     int* __restrict__ rowptr, int N)
{
    __shared__ int s[256];
    int t = threadIdx.x;
    int d = (t < nb) ? partials[t] : 0;
    s[t] = d;
    __syncthreads();
    #pragma unroll
    for (int off = 1; off < 256; off <<= 1) {
        int v = (t >= off) ? s[t - off] : 0;
        __syncthreads();
        s[t] += v;
        __syncthreads();
    }
    if (t < nb) partials[t] = s[t] - d;     // exclusive
    if (t == 255) rowptr[N] = s[255];       // grand total = E
}

__global__ void chunk_scan_kernel(const int* __restrict__ deg,
                                  const int* __restrict__ partials,
                                  int* __restrict__ rowptr, int* __restrict__ cursor, int N)
{
    __shared__ int s[256];
    int t = threadIdx.x;
    int i = blockIdx.x * 256 + t;
    int d = (i < N) ? deg[i] : 0;
    s[t] = d;
    __syncthreads();
    #pragma unroll
    for (int off = 1; off < 256; off <<= 1) {
        int v = (t >= off) ? s[t - off] : 0;
        __syncthreads();
        s[t] += v;
        __syncthreads();
    }
    if (i < N) {
        int val = partials[blockIdx.x] + s[t] - d;   // exclusive global prefix
        rowptr[i] = val;
        cursor[i] = val;
    }
}

__global__ void fill_kernel(const int* __restrict__ row, const int* __restrict__ col,
                            const float* __restrict__ ew,
                            int* __restrict__ cursor,
                            int* __restrict__ esrc, float* __restrict__ ewr, int E)
{
    int e = blockIdx.x * blockDim.x + threadIdx.x;
    if (e >= E) return;
    int c = col[e];
    int p = atomicAdd(&cursor[c], 1);
    esrc[p] = row[e];
    ewr[p]  = ew[e];
}

// ---------------- fused aggregate (CSR fp16 gather) + PReLU + pool ----------------
// R10 form exactly: serial edge loop, 4 nodes/warp, separate esrc/ewr streams.
__device__ __forceinline__ void red_add_v4(float* dst, float4 v) {
    asm volatile("red.global.add.v4.f32 [%0], {%1, %2, %3, %4};"
                 :: "l"(dst), "f"(v.x), "f"(v.y), "f"(v.z), "f"(v.w)
                 : "memory");
}

__global__ __launch_bounds__(256) void aggregate_pool_kernel(
    const __half* __restrict__ t, const int* __restrict__ rowptr,
    const int* __restrict__ esrc, const float* __restrict__ ewr,
    const float* __restrict__ aptr, const int* __restrict__ batch,
    float* __restrict__ hout, float* __restrict__ hg, int N, int loff)
{
    int wid  = (blockIdx.x * blockDim.x + threadIdx.x) >> 5;
    int lane = threadIdx.x & 31;
    int n0 = wid * 4;
    if (n0 >= N) return;
    float alpha = __ldg(aptr);

    float4 run = make_float4(0.f, 0.f, 0.f, 0.f);
    int curg = -1;
    int nend = n0 + 4; if (nend > N) nend = N;

    for (int n = n0; n < nend; n++) {
        int jb = __ldg(rowptr + n);
        int je = __ldg(rowptr + n + 1);
        float4 acc = make_float4(0.f, 0.f, 0.f, 0.f);
        for (int j = jb; j < je; j++) {
            int r   = __ldg(esrc + j);
            float w = __ldg(ewr + j);
            uint2 u = __ldg((const uint2*)(t + (size_t)r * DD) + lane);
            float2 f01 = __half22float2(*reinterpret_cast<__half2*>(&u.x));
            float2 f23 = __half22float2(*reinterpret_cast<__half2*>(&u.y));
            acc.x = fmaf(f01.x, w, acc.x);
            acc.y = fmaf(f01.y, w, acc.y);
            acc.z = fmaf(f23.x, w, acc.z);
            acc.w = fmaf(f23.y, w, acc.w);
        }
        float4 p;
        p.x = acc.x >= 0.f ? acc.x : alpha * acc.x;
        p.y = acc.y >= 0.f ? acc.y : alpha * acc.y;
        p.z = acc.z >= 0.f ? acc.z : alpha * acc.z;
        p.w = acc.w >= 0.f ? acc.w : alpha * acc.w;
        *(float4*)(hout + (size_t)n * DD + lane * 4) = p;

        int g = __ldg(batch + n);
        if (g != curg) {
            if (curg >= 0)
                red_add_v4(hg + (size_t)curg * (3 * DD) + loff + lane * 4, run);
            curg = g;
            run = p;
        } else {
            run.x += p.x; run.y += p.y; run.z += p.z; run.w += p.w;
        }
    }
    if (curg >= 0)
        red_add_v4(hg + (size_t)curg * (3 * DD) + loff + lane * 4, run);
}

// ---------------- launch ----------------
extern "C" void kernel_launch(void* const* d_in, const int* in_sizes, int n_in,
                              void* d_out, int out_size)
{
    const float* feat  = (const float*)d_in[0];
    const float* ew    = (const float*)d_in[1];
    const float* W[3]  = {(const float*)d_in[2], (const float*)d_in[3], (const float*)d_in[4]};
    const float* a[3]  = {(const float*)d_in[5], (const float*)d_in[6], (const float*)d_in[7]};
    const int*   eidx  = (const int*)d_in[8];
    const int*   batch = (const int*)d_in[9];

    const int N = in_sizes[0] / DD;      // 40000
    const int E = in_sizes[1];           // 640000
    const int* rowp = eidx;
    const int* colp = eidx + E;

    float *h_ptr, *ewr_ptr;
    __half* t_ptr;
    int *deg_ptr, *rowptr_ptr, *cursor_ptr, *partials_ptr, *esrc_ptr;
    uint32_t* wf_ptr;
    cudaGetSymbolAddress((void**)&t_ptr,       g_t);
    cudaGetSymbolAddress((void**)&h_ptr,       g_h);
    cudaGetSymbolAddress((void**)&deg_ptr,     g_deg);
    cudaGetSymbolAddress((void**)&rowptr_ptr,  g_rowptr);
    cudaGetSymbolAddress((void**)&cursor_ptr,  g_cursor);
    cudaGetSymbolAddress((void**)&partials_ptr,g_partials);
    cudaGetSymbolAddress((void**)&esrc_ptr,    g_esrc);
    cudaGetSymbolAddress((void**)&ewr_ptr,     g_ewr);
    cudaGetSymbolAddress((void**)&wf_ptr,      g_wfrag);

    float* h_out = (float*)d_out;                         // (N, 128)
    float* hg    = (float*)d_out + (size_t)N * DD;        // (128, 384)

    cudaStream_t s = 0;
    cudaMemsetAsync(hg, 0, (size_t)NGRAPHS * 3 * DD * sizeof(float), s);   // launch 1
    cudaMemsetAsync(deg_ptr, 0, (size_t)N * sizeof(int), s);               // launch 2

    const int nb = (N + 255) / 256;      // 157 chunks
    const int gemm_blocks = (N + 63) / 64;
    const int agg_warps   = (N + 3) / 4;
    const int agg_blocks  = (agg_warps * 32 + 255) / 256;

    // Ordered so that launch #6 (ncu -s 5 -c 1) is the GEMM.
    wconv_kernel<<<(3 * 8192 + 255) / 256, 256, 0, s>>>(W[0], W[1], W[2], wf_ptr);  // 3
    hist_kernel<<<(E + 255) / 256, 256, 0, s>>>(colp, deg_ptr, E);                  // 4
    block_sum_kernel<<<nb, 256, 0, s>>>(deg_ptr, partials_ptr, N);                  // 5
    gemm_mma_kernel<<<gemm_blocks, 256, 0, s>>>(feat, wf_ptr, t_ptr, N);            // 6 <- profiled
    scan_partials_kernel<<<1, 256, 0, s>>>(partials_ptr, nb, rowptr_ptr, N);        // 7
    chunk_scan_kernel<<<nb, 256, 0, s>>>(deg_ptr, partials_ptr, rowptr_ptr, cursor_ptr, N); // 8
    fill_kernel<<<(E + 255) / 256, 256, 0, s>>>(rowp, colp, ew, cursor_ptr, esrc_ptr, ewr_ptr, E); // 9

    aggregate_pool_kernel<<<agg_blocks, 256, 0, s>>>(
        t_ptr, rowptr_ptr, esrc_ptr, ewr_ptr, a[0], batch, h_ptr, hg, N, 0);        // 10

    for (int l = 1; l < 3; l++) {
        gemm_mma_kernel<<<gemm_blocks, 256, 0, s>>>(h_ptr, wf_ptr + (size_t)l * 8192, t_ptr, N);
        float* ho = (l == 2) ? h_out : h_ptr;
        aggregate_pool_kernel<<<agg_blocks, 256, 0, s>>>(
            t_ptr, rowptr_ptr, esrc_ptr, ewr_ptr, a[l], batch, ho, hg, N, l * DD);
    }
}

// round 14
// speedup vs baseline: 1.2584x; 1.0197x over previous
#include <cuda_runtime.h>
#include <cuda_fp16.h>
#include <cstdint>

#define NNODES 40000
#define NEDGES_MAX 640000
#define NGRAPHS 128
#define DD 128

// ---------------- scratch (no allocations allowed) ----------------
__device__ __half g_t[(size_t)NNODES * DD];   // GEMM output (fp16 gather payload)
__device__ __half g_hf[(size_t)NNODES * DD];  // fp16 hidden state (GEMM input)
__device__ int    g_deg[NNODES];
__device__ int    g_rowptr[NNODES + 1];
__device__ int    g_cursor[NNODES];
__device__ int    g_partials[256];
__device__ int    g_esrc[NEDGES_MAX];
__device__ float  g_ewr[NEDGES_MAX];
// W fragments (fp16x2 packed — W quantized to fp16), fragment-ordered
__device__ uint32_t g_wfrag[3][8192];

// ======================= fp16 tensor GEMM (mma.sync m16n8k16) ============
// t[M,128] = A[M,128] @ fp16(W)[128,128]^T, A already fp16 (exact input).
// BM=64 (625 CTAs ~ 1 wave @4 CTAs/SM), 8 warps, warp tile 32x32.

__device__ __forceinline__ uint32_t f16x2_pack(float even, float odd) {
    __half2 h = __float22half2_rn(make_float2(even, odd));  // .x = even (low half)
    return *reinterpret_cast<uint32_t*>(&h);
}

__device__ __forceinline__ void mma_f16(float* c, const uint32_t* a, const uint32_t* b) {
    asm volatile(
        "mma.sync.aligned.m16n8k16.row.col.f32.f16.f16.f32 "
        "{%0,%1,%2,%3}, {%4,%5,%6,%7}, {%8,%9}, {%0,%1,%2,%3};"
        : "+f"(c[0]), "+f"(c[1]), "+f"(c[2]), "+f"(c[3])
        : "r"(a[0]), "r"(a[1]), "r"(a[2]), "r"(a[3]), "r"(b[0]), "r"(b[1]));
}

__global__ __launch_bounds__(256, 4) void gemm_mma_kernel(
    const __half* __restrict__ A, const uint32_t* __restrict__ wf,
    __half* __restrict__ out, int M)
{
    __shared__ uint32_t smem[4096];      // 64 rows x 64 f16x2 = 16 KB
    const int tid  = threadIdx.x;
    const int wid  = tid >> 5;
    const int lane = tid & 31;
    const int wm   = wid >> 2;          // 0..1  (32-row group)
    const int wn   = wid & 3;           // 0..3  (32-col group)
    const int rbase = blockIdx.x * 64;

    float C[2][4][4];
    #pragma unroll
    for (int i = 0; i < 2; i++)
        #pragma unroll
        for (int j = 0; j < 4; j++)
            #pragma unroll
            for (int q = 0; q < 4; q++) C[i][j][q] = 0.f;

    // ---- stage A (64x128 fp16) into fragment-ordered SMEM (no conversion) ----
    #pragma unroll
    for (int rep = 0; rep < 4; rep++) {
        int idx = rep * 256 + tid;          // 0..1023
        int row = idx >> 4;                 // 0..63
        int qq  = idx & 15;                 // uint4 index (4 pairs = 8 fp16)
        int gr  = rbase + row;
        uint4 v = (gr < M)
            ? __ldg((const uint4*)(A + (size_t)gr * DD) + qq)
            : make_uint4(0u, 0u, 0u, 0u);
        int mblk = row >> 4, r = row & 15;
        int gid = r & 7, rb = r >> 3;
        uint32_t e[4] = {v.x, v.y, v.z, v.w};
        #pragma unroll
        for (int p = 0; p < 4; p++) {
            int c2 = qq * 4 + p;            // pair index 0..63
            int ks = c2 >> 3;
            int tf = c2 & 3;
            int ii = (((c2 >> 2) & 1) << 1) | rb;
            int slot = ((gid << 2) | tf) ^ ks;  // lane swizzle vs ks
            smem[((mblk * 8 + ks) * 32 + slot) * 4 + ii] = e[p];
        }
    }
    __syncthreads();

    // ---- 8 k16-steps of m16n8k16, single term ----
    #pragma unroll
    for (int ks = 0; ks < 8; ks++) {
        uint32_t Af[2][4], Bf[4][2];
        #pragma unroll
        for (int fm = 0; fm < 2; fm++) {
            int mblk = wm * 2 + fm;
            int base = ((mblk * 8 + ks) * 32 + (lane ^ ks)) * 4;
            uint4 h = *(const uint4*)(smem + base);
            Af[fm][0] = h.x; Af[fm][1] = h.y; Af[fm][2] = h.z; Af[fm][3] = h.w;
        }
        #pragma unroll
        for (int fn = 0; fn < 4; fn++) {
            int nblk = wn * 4 + fn;
            int boff = ((nblk * 8 + ks) * 32 + lane) * 2;
            uint2 h = __ldg((const uint2*)(wf + boff));
            Bf[fn][0] = h.x; Bf[fn][1] = h.y;
        }
        #pragma unroll
        for (int fm = 0; fm < 2; fm++)
            #pragma unroll
            for (int fn = 0; fn < 4; fn++)
                mma_f16(C[fm][fn], Af[fm], Bf[fn]);
    }

    // ---- epilogue: write C frags as fp16 ----
    #pragma unroll
    for (int fm = 0; fm < 2; fm++) {
        int row0 = rbase + wm * 32 + fm * 16 + (lane >> 2);
        #pragma unroll
        for (int fn = 0; fn < 4; fn++) {
            int col = wn * 32 + fn * 8 + (lane & 3) * 2;
            if (row0 < M)
                *(__half2*)(out + (size_t)row0 * DD + col) =
                    __float22half2_rn(make_float2(C[fm][fn][0], C[fm][fn][1]));
            if (row0 + 8 < M)
                *(__half2*)(out + (size_t)(row0 + 8) * DD + col) =
                    __float22half2_rn(make_float2(C[fm][fn][2], C[fm][fn][3]));
        }
    }
}

// ---------------- feat -> fp16 conversion (once) ----------------
__global__ void aconv_kernel(const float* __restrict__ A,
                             __half* __restrict__ hf, int M)
{
    int idx = blockIdx.x * blockDim.x + threadIdx.x;   // 0..M*32-1
    if (idx >= M * 32) return;
    int row = idx >> 5;
    int q   = idx & 31;                                // float4 index
    float4 v = __ldg((const float4*)(A + (size_t)row * DD) + q);
    uint2 o = make_uint2(f16x2_pack(v.x, v.y), f16x2_pack(v.z, v.w));
    ((uint2*)(hf + (size_t)row * DD))[q] = o;
}

// ---------------- W fragment precompute (once per call) ----------------
__global__ void wconv_kernel(const float* __restrict__ W0,
                             const float* __restrict__ W1,
                             const float* __restrict__ W2,
                             uint32_t* __restrict__ wf)   // [3][8192]
{
    int idx = blockIdx.x * blockDim.x + threadIdx.x;      // 0..24575
    if (idx >= 3 * 8192) return;
    int l   = idx >> 13;
    int rem = idx & 8191;
    int n   = rem >> 6;          // 0..127 (out feature)
    int t   = rem & 63;          // k-pair index, k = 2t
    const float* W = (l == 0) ? W0 : (l == 1) ? W1 : W2;
    float x0 = __ldg(W + (size_t)n * DD + 2 * t);
    float x1 = __ldg(W + (size_t)n * DD + 2 * t + 1);
    uint32_t hi = f16x2_pack(x0, x1);
    int ks  = t >> 3;
    int tf  = t & 3;
    int ii  = (t >> 2) & 1;
    int nblk = n >> 3, gid = n & 7;
    int lane = gid * 4 + tf;
    int off = ((nblk * 8 + ks) * 32 + lane) * 2 + ii;
    wf[l * 8192 + off] = hi;
}

// ---------------- CSR build: histogram + 2-level scan + reorder ----------------
__global__ void hist_kernel(const int* __restrict__ col, int* __restrict__ deg, int E)
{
    int e = blockIdx.x * blockDim.x + threadIdx.x;
    if (e < E) atomicAdd(&deg[col[e]], 1);
}

__global__ void block_sum_kernel(const int* __restrict__ deg, int* __restrict__ partials, int N)
{
    __shared__ int s[256];
    int i = blockIdx.x * 256 + threadIdx.x;
    s[threadIdx.x] = (i < N) ? deg[i] : 0;
    __syncthreads();
    for (int off = 128; off > 0; off >>= 1) {
        if (threadIdx.x < off) s[threadIdx.x] += s[threadIdx.x + off];
        __syncthreads();
    }
    if (threadIdx.x == 0) partials[blockIdx.x] = s[0];
}

__global__ void scan_partials_kernel(int* __restrict__ partials, int nb,
                                     int* __restrict__ rowptr, int N)
{
    __shared__ int s[256];
    int t = threadIdx.x;
    int d = (t < nb) ? partials[t] : 0;
    s[t] = d;
    __syncthreads();
    #pragma unroll
    for (int off = 1; off < 256; off <<= 1) {
        int v = (t >= off) ? s[t - off] : 0;
        __syncthreads();
        s[t] += v;
        __syncthreads();
    }
    if (t < nb) partials[t] = s[t] - d;     // exclusive
    if (t == 255) rowptr[N] = s[255];       // grand total = E
}

__global__ void chunk_scan_kernel(const int* __restrict__ deg,
                                  const int* __restrict__ partials,
                                  int* __restrict__ rowptr, int* __restrict__ cursor, int N)
{
    __shared__ int s[256];
    int t = threadIdx.x;
    int i = blockIdx.x * 256 + t;
    int d = (i < N) ? deg[i] : 0;
    s[t] = d;
    __syncthreads();
    #pragma unroll
    for (int off = 1; off < 256; off <<= 1) {
        int v = (t >= off) ? s[t - off] : 0;
        __syncthreads();
        s[t] += v;
        __syncthreads();
    }
    if (i < N) {
        int val = partials[blockIdx.x] + s[t] - d;   // exclusive global prefix
        rowptr[i] = val;
        cursor[i] = val;
    }
}

__global__ void fill_kernel(const int* __restrict__ row, const int* __restrict__ col,
                            const float* __restrict__ ew,
                            int* __restrict__ cursor,
                            int* __restrict__ esrc, float* __restrict__ ewr, int E)
{
    int e = blockIdx.x * blockDim.x + threadIdx.x;
    if (e >= E) return;
    int c = col[e];
    int p = atomicAdd(&cursor[c], 1);
    esrc[p] = row[e];
    ewr[p]  = ew[e];
}

// ---------------- fused aggregate (CSR fp16 gather) + PReLU + pool ----------------
// R10 form: serial edge loop, 4 nodes/warp. Output: fp16 hidden (layers 0,1)
// or fp32 d_out (layer 2).
__device__ __forceinline__ void red_add_v4(float* dst, float4 v) {
    asm volatile("red.global.add.v4.f32 [%0], {%1, %2, %3, %4};"
                 :: "l"(dst), "f"(v.x), "f"(v.y), "f"(v.z), "f"(v.w)
                 : "memory");
}

__global__ __launch_bounds__(256) void aggregate_pool_kernel(
    const __half* __restrict__ t, const int* __restrict__ rowptr,
    const int* __restrict__ esrc, const float* __restrict__ ewr,
    const float* __restrict__ aptr, const int* __restrict__ batch,
    float* __restrict__ hout, __half* __restrict__ hfout,
    float* __restrict__ hg, int N, int loff)
{
    int wid  = (blockIdx.x * blockDim.x + threadIdx.x) >> 5;
    int lane = threadIdx.x & 31;
    int n0 = wid * 4;
    if (n0 >= N) return;
    float alpha = __ldg(aptr);

    float4 run = make_float4(0.f, 0.f, 0.f, 0.f);
    int curg = -1;
    int nend = n0 + 4; if (nend > N) nend = N;

    for (int n = n0; n < nend; n++) {
        int jb = __ldg(rowptr + n);
        int je = __ldg(rowptr + n + 1);
        float4 acc = make_float4(0.f, 0.f, 0.f, 0.f);
        for (int j = jb; j < je; j++) {
            int r   = __ldg(esrc + j);
            float w = __ldg(ewr + j);
            uint2 u = __ldg((const uint2*)(t + (size_t)r * DD) + lane);
            float2 f01 = __half22float2(*reinterpret_cast<__half2*>(&u.x));
            float2 f23 = __half22float2(*reinterpret_cast<__half2*>(&u.y));
            acc.x = fmaf(f01.x, w, acc.x);
            acc.y = fmaf(f01.y, w, acc.y);
            acc.z = fmaf(f23.x, w, acc.z);
            acc.w = fmaf(f23.y, w, acc.w);
        }
        float4 p;
        p.x = acc.x >= 0.f ? acc.x : alpha * acc.x;
        p.y = acc.y >= 0.f ? acc.y : alpha * acc.y;
        p.z = acc.z >= 0.f ? acc.z : alpha * acc.z;
        p.w = acc.w >= 0.f ? acc.w : alpha * acc.w;
        if (hfout) {
            uint2 o = make_uint2(f16x2_pack(p.x, p.y), f16x2_pack(p.z, p.w));
            ((uint2*)(hfout + (size_t)n * DD))[lane] = o;
        } else {
            *(float4*)(hout + (size_t)n * DD + lane * 4) = p;
        }

        int g = __ldg(batch + n);
        if (g != curg) {
            if (curg >= 0)
                red_add_v4(hg + (size_t)curg * (3 * DD) + loff + lane * 4, run);
            curg = g;
            run = p;
        } else {
            run.x += p.x; run.y += p.y; run.z += p.z; run.w += p.w;
        }
    }
    if (curg >= 0)
        red_add_v4(hg + (size_t)curg * (3 * DD) + loff + lane * 4, run);
}

// ---------------- launch ----------------
extern "C" void kernel_launch(void* const* d_in, const int* in_sizes, int n_in,
                              void* d_out, int out_size)
{
    const float* feat  = (const float*)d_in[0];
    const float* ew    = (const float*)d_in[1];
    const float* W[3]  = {(const float*)d_in[2], (const float*)d_in[3], (const float*)d_in[4]};
    const float* a[3]  = {(const float*)d_in[5], (const float*)d_in[6], (const float*)d_in[7]};
    const int*   eidx  = (const int*)d_in[8];
    const int*   batch = (const int*)d_in[9];

    const int N = in_sizes[0] / DD;      // 40000
    const int E = in_sizes[1];           // 640000
    const int* rowp = eidx;
    const int* colp = eidx + E;

    float *ewr_ptr;
    __half *t_ptr, *hf_ptr;
    int *deg_ptr, *rowptr_ptr, *cursor_ptr, *partials_ptr, *esrc_ptr;
    uint32_t* wf_ptr;
    cudaGetSymbolAddress((void**)&t_ptr,       g_t);
    cudaGetSymbolAddress((void**)&hf_ptr,      g_hf);
    cudaGetSymbolAddress((void**)&deg_ptr,     g_deg);
    cudaGetSymbolAddress((void**)&rowptr_ptr,  g_rowptr);
    cudaGetSymbolAddress((void**)&cursor_ptr,  g_cursor);
    cudaGetSymbolAddress((void**)&partials_ptr,g_partials);
    cudaGetSymbolAddress((void**)&esrc_ptr,    g_esrc);
    cudaGetSymbolAddress((void**)&ewr_ptr,     g_ewr);
    cudaGetSymbolAddress((void**)&wf_ptr,      g_wfrag);

    float* h_out = (float*)d_out;                         // (N, 128)
    float* hg    = (float*)d_out + (size_t)N * DD;        // (128, 384)

    cudaStream_t s = 0;
    cudaMemsetAsync(hg, 0, (size_t)NGRAPHS * 3 * DD * sizeof(float), s);   // launch 1
    cudaMemsetAsync(deg_ptr, 0, (size_t)N * sizeof(int), s);               // launch 2

    const int nb = (N + 255) / 256;      // 157 chunks
    const int gemm_blocks = (N + 63) / 64;
    const int agg_warps   = (N + 3) / 4;
    const int agg_blocks  = (agg_warps * 32 + 255) / 256;

    // Ordered so that launch #6 (ncu -s 5 -c 1) is the GEMM.
    wconv_kernel<<<(3 * 8192 + 255) / 256, 256, 0, s>>>(W[0], W[1], W[2], wf_ptr);  // 3
    aconv_kernel<<<(N * 32 + 255) / 256, 256, 0, s>>>(feat, hf_ptr, N);             // 4
    hist_kernel<<<(E + 255) / 256, 256, 0, s>>>(colp, deg_ptr, E);                  // 5
    gemm_mma_kernel<<<gemm_blocks, 256, 0, s>>>(hf_ptr, wf_ptr, t_ptr, N);          // 6 <- profiled
    block_sum_kernel<<<nb, 256, 0, s>>>(deg_ptr, partials_ptr, N);                  // 7
    scan_partials_kernel<<<1, 256, 0, s>>>(partials_ptr, nb, rowptr_ptr, N);        // 8
    chunk_scan_kernel<<<nb, 256, 0, s>>>(deg_ptr, partials_ptr, rowptr_ptr, cursor_ptr, N); // 9
    fill_kernel<<<(E + 255) / 256, 256, 0, s>>>(rowp, colp, ew, cursor_ptr, esrc_ptr, ewr_ptr, E); // 10

    // layer 0: aggregate -> fp16 hidden
    aggregate_pool_kernel<<<agg_blocks, 256, 0, s>>>(
        t_ptr, rowptr_ptr, esrc_ptr, ewr_ptr, a[0], batch,
        nullptr, hf_ptr, hg, N, 0);                                                 // 11

    // layer 1
    gemm_mma_kernel<<<gemm_blocks, 256, 0, s>>>(hf_ptr, wf_ptr + 8192, t_ptr, N);
    aggregate_pool_kernel<<<agg_blocks, 256, 0, s>>>(
        t_ptr, rowptr_ptr, esrc_ptr, ewr_ptr, a[1], batch,
        nullptr, hf_ptr, hg, N, DD);

    // layer 2: aggregate -> fp32 d_out
    gemm_mma_kernel<<<gemm_blocks, 256, 0, s>>>(hf_ptr, wf_ptr + 16384, t_ptr, N);
    aggregate_pool_kernel<<<agg_blocks, 256, 0, s>>>(
        t_ptr, rowptr_ptr, esrc_ptr, ewr_ptr, a[2], batch,
        h_out, nullptr, hg, N, 2 * DD);
}